// round 13
// baseline (speedup 1.0000x reference)
#include <cuda_runtime.h>
#include <cuda_fp16.h>
#include <stdint.h>

// RNNWithCheckpoint: T=512, B=128, H=1024, L=4 multi-layer tanh RNN.
// R11: critical-path decomposition. Per layer: 16 hh-CTAs run the recurrence
// h[t] = tanh(pre[t] + h[t-1] @ W_hh^T) (full K=1024, NO split-K, NO cluster,
// NO DSMEM); 16 ih-CTAs precompute pre[t] = input @ W_ih^T + bias one
// wavefront slot ahead (skew-2), parity-buffered in global fp32.
// Progress flags per CTA; R7's proven 3-buffer 16-chunk mainloop.

#define T_STEPS 512
#define BATCH   128
#define HID     1024
#define LAYERS  4
#define NCTA    128

#define SM_W   0            // 64 rows x 2048B, XOR-swizzled = 131072
#define SM_AB  131072       // 3 A bufs, each 128 rows x 128B = 16384
#define ABUF   16384
#define SMEM_BYTES 180224

// Static device scratch (no cudaMalloc allowed)
__device__ __align__(16) __half g_Wh[LAYERS * 2 * HID * HID];   // [l][ks][n][k] ks0=ih ks1=hh
__device__ __align__(16) __half g_xh[(size_t)T_STEPS * BATCH * HID];
__device__ __align__(16) float  g_bias[LAYERS * HID];
__device__ __align__(16) __half g_act[2][LAYERS * BATCH * HID]; // slot = t&1
__device__ __align__(16) float  g_pre[2 * LAYERS * BATCH * HID]; // slot = t&1
__device__ unsigned g_flags[NCTA * 32];   // F[bx] = completed steps

// ------------------------------------------------------------- helpers ----
__device__ __forceinline__ uint32_t smem_u32(const void* p) {
    uint32_t a;
    asm("{ .reg .u64 t; cvta.to.shared.u64 t, %1; cvt.u32.u64 %0, t; }"
        : "=r"(a) : "l"(p));
    return a;
}
__device__ __forceinline__ void cp16(uint32_t dst, const void* src) {
    asm volatile("cp.async.cg.shared.global [%0], [%1], 16;"
                 :: "r"(dst), "l"(src) : "memory");
}
__device__ __forceinline__ void ldsm4(uint32_t* r, uint32_t a) {
    asm volatile("ldmatrix.sync.aligned.m8n8.x4.shared.b16 {%0,%1,%2,%3}, [%4];"
                 : "=r"(r[0]), "=r"(r[1]), "=r"(r[2]), "=r"(r[3]) : "r"(a));
}
__device__ __forceinline__ void mma16816(float* c, const uint32_t* a,
                                         uint32_t b0, uint32_t b1) {
    asm volatile(
        "mma.sync.aligned.m16n8k16.row.col.f32.f16.f16.f32 "
        "{%0,%1,%2,%3}, {%4,%5,%6,%7}, {%8,%9}, {%0,%1,%2,%3};"
        : "+f"(c[0]), "+f"(c[1]), "+f"(c[2]), "+f"(c[3])
        : "r"(a[0]), "r"(a[1]), "r"(a[2]), "r"(a[3]), "r"(b0), "r"(b1));
}
__device__ __forceinline__ unsigned ldflag(int cta) {
    unsigned v;
    asm volatile("ld.global.cg.u32 %0, [%1];"
                 : "=r"(v) : "l"(g_flags + (size_t)cta * 32) : "memory");
    return v;
}
// Poll: lanes < nl watch flag (base + stride*lane + off) >= tgt.
__device__ __forceinline__ void pollS(int base, int off, int target, int lane, int nl)
{
    if (target <= 0) return;
    unsigned tgt = (unsigned)target;
    for (;;) {
        bool ok = (lane < nl) ? (ldflag(base + 2 * lane + off) >= tgt) : true;
        if (__all_sync(0xffffffffu, ok)) break;
        __nanosleep(40);
    }
}
__device__ __forceinline__ float tanh_mufu(float x) {
    float y;
    asm("tanh.approx.f32 %0, %1;" : "=f"(y) : "f"(x));
    return y;
}

// ---------------------------------------------------------------- prep ----
__global__ void __launch_bounds__(256) prep_kernel(
    const float* __restrict__ x,
    const float* __restrict__ Wih, const float* __restrict__ Whh,
    const float* __restrict__ bih, const float* __restrict__ bhh)
{
    int tid  = blockIdx.x * blockDim.x + threadIdx.x;
    int nthr = gridDim.x * blockDim.x;
    const int NW = LAYERS * HID * HID;
    for (int i = tid; i < NW; i += nthr) {
        int l  = i >> 20;
        int nk = i & (HID * HID - 1);
        g_Wh[((size_t)(l * 2 + 0) << 20) + nk] = __float2half(Wih[i]);
        g_Wh[((size_t)(l * 2 + 1) << 20) + nk] = __float2half(Whh[i]);
    }
    const size_t NX4 = (size_t)T_STEPS * BATCH * HID / 4;
    for (size_t i = tid; i < NX4; i += nthr) {
        float4 v = *(const float4*)(x + i * 4);
        *(__half2*)&g_xh[i * 4]     = __floats2half2_rn(v.x, v.y);
        *(__half2*)&g_xh[i * 4 + 2] = __floats2half2_rn(v.z, v.w);
    }
    for (int i = tid; i < LAYERS * HID; i += nthr) g_bias[i] = bih[i] + bhh[i];
    for (int i = tid; i < LAYERS * BATCH * HID; i += nthr) {
        g_act[0][i] = __float2half(0.0f);
        g_act[1][i] = __float2half(0.0f);
    }
    for (int i = tid; i < NCTA * 32; i += nthr) g_flags[i] = 0;
}

// ----------------------------------------------------------- persistent ---
// bx: l = bx>>5, nt = (bx>>1)&15, role = bx&1 (0 = hh critical, 1 = ih).
__global__ void __launch_bounds__(256)
rnn_persistent(float* __restrict__ out)
{
    extern __shared__ char sh[];
    const uint32_t sb = smem_u32(sh);

    const int bx   = blockIdx.x;
    const int l    = bx >> 5;
    const int nt   = (bx >> 1) & 15;
    const int role = bx & 1;            // 0 = hh (critical), 1 = ih (ahead)
    const int tid  = threadIdx.x;
    const int wid  = tid >> 5, lane = tid & 31;
    const int g    = lane >> 2, tq = lane & 3;
    const int wm   = (wid >> 1) * 32;   // 4 m-groups of 32 rows
    const int wn   = (wid & 1) * 32;    // 2 n-groups of 32 cols

    // ---- resident weight slice: 64 n-rows x 1024 k halves, XOR-swizzled
    {
        const int ks = role ? 0 : 1;    // hh uses W_hh (ks=1), ih uses W_ih
        const __half* wsrc = g_Wh + (((size_t)(l * 2 + ks) * HID) + nt * 64) * HID;
        for (int i = tid; i < 8192; i += 256) {
            int n = i >> 7, u = i & 127;
            uint32_t dst = sb + SM_W + (uint32_t)(n * 2048 + ((u >> 3) << 7)
                           + (((u & 7) ^ (n & 7)) << 4));
            cp16(dst, wsrc + (size_t)n * HID + u * 8);
        }
        asm volatile("cp.async.commit_group;" ::: "memory");
        asm volatile("cp.async.wait_group 0;" ::: "memory");
        __syncthreads();
    }

    // ---- per-thread constant addressing (R7 mainloop geometry) ----
    const int rA  = wm + (lane & 15);
    const int h16 = lane >> 4;
    const int sAx = rA & 7;
    const int sBx = (wn + (lane & 15)) & 7;
    const uint32_t aTail = (uint32_t)(rA * 128);
    int aoff[4], boff[4];
    #pragma unroll
    for (int j = 0; j < 4; j++) {
        aoff[j] = ((2 * j + h16) ^ sAx) << 4;
        boff[j] = ((2 * j + h16) ^ sBx) << 4;
    }
    const uint32_t wb0 = sb + SM_W + (uint32_t)((wn + (lane & 15)) * 2048);
    const uint32_t wb1 = wb0 + 16 * 2048;

    const int fr = tid >> 3, fu = tid & 7;
    const uint32_t fTail = (uint32_t)(fr * 128 + ((fu ^ (fr & 7)) << 4));
    const int fGoff = fr * HID + fu * 8;

    float2 bs[4];
    #pragma unroll
    for (int nti = 0; nti < 4; nti++)
        bs[nti] = *(const float2*)&g_bias[l * HID + nt * 64 + wn + nti * 8 + tq * 2];

    #pragma unroll 1
    for (int t = 0; t < T_STEPS; t++) {
        // ---- dependency gates (warps poll in parallel) ----
        if (role == 0) {   // hh critical path
            if (wid == 0)               pollS(l * 32, 0, t, lane, 16);        // own h[t-1]
            else if (wid == 1)          pollS(l * 32 + 2 * nt, 1, t + 1, lane, 1); // pre[t]
            else if (wid == 2 && l < 3) pollS((l + 1) * 32, 1, t - 1, lane, 16);   // WAR act
        } else {           // ih, one slot ahead
            if (wid == 0 && l > 0)      pollS((l - 1) * 32, 0, t + 1, lane, 16);   // h[l-1][t]
            else if (wid == 1)          pollS(l * 32 + 2 * nt, 0, t - 1, lane, 1); // WAR pre
        }
        __syncthreads();

        const __half* src;
        if (role == 0)   src = g_act[(t & 1) ^ 1] + (size_t)l * BATCH * HID;   // h[t-1]
        else if (l == 0) src = g_xh + (size_t)t * BATCH * HID;                 // x[t]
        else             src = g_act[t & 1] + (size_t)(l - 1) * BATCH * HID;   // h[l-1][t]
        const __half* gp0 = src + fGoff;

        // prologue fills: chunk 0 -> buf0, chunk 1 -> buf1
        #pragma unroll
        for (int c0 = 0; c0 < 2; c0++) {
            uint32_t d = sb + SM_AB + (uint32_t)(c0 * ABUF) + fTail;
            const __half* gp = gp0 + c0 * 64;
            cp16(d,         gp);
            cp16(d + 4096,  gp + 32 * HID);
            cp16(d + 8192,  gp + 64 * HID);
            cp16(d + 12288, gp + 96 * HID);
            asm volatile("cp.async.commit_group;" ::: "memory");
        }

        float acc[2][4][4];
        #pragma unroll
        for (int i = 0; i < 2; i++)
            #pragma unroll
            for (int j = 0; j < 4; j++)
                #pragma unroll
                for (int k = 0; k < 4; k++) acc[i][j][k] = 0.0f;

        int b = 0, fb = 2;
        #pragma unroll 1
        for (int ch = 0; ch < 16; ch++) {
            if (ch < 15) asm volatile("cp.async.wait_group 1;" ::: "memory");
            else         asm volatile("cp.async.wait_group 0;" ::: "memory");
            __syncthreads();

            if (ch < 14) {
                uint32_t d = sb + SM_AB + (uint32_t)(fb * ABUF) + fTail;
                const __half* gp = gp0 + (ch + 2) * 64;
                cp16(d,         gp);
                cp16(d + 4096,  gp + 32 * HID);
                cp16(d + 8192,  gp + 64 * HID);
                cp16(d + 12288, gp + 96 * HID);
                asm volatile("cp.async.commit_group;" ::: "memory");
                fb = (fb == 2) ? 0 : fb + 1;
            }

            const uint32_t abA = sb + SM_AB + (uint32_t)(b * ABUF) + aTail;
            const uint32_t kb  = (uint32_t)(ch << 7);
            #pragma unroll
            for (int j = 0; j < 4; j++) {
                uint32_t a0[4], a1[4], b0[4], b1[4];
                ldsm4(a0, abA + aoff[j]);
                ldsm4(a1, abA + 2048 + aoff[j]);
                ldsm4(b0, wb0 + kb + boff[j]);
                ldsm4(b1, wb1 + kb + boff[j]);
                mma16816(acc[0][0], a0, b0[0], b0[2]);
                mma16816(acc[0][1], a0, b0[1], b0[3]);
                mma16816(acc[0][2], a0, b1[0], b1[2]);
                mma16816(acc[0][3], a0, b1[1], b1[3]);
                mma16816(acc[1][0], a1, b0[0], b0[2]);
                mma16816(acc[1][1], a1, b0[1], b0[3]);
                mma16816(acc[1][2], a1, b1[0], b1[2]);
                mma16816(acc[1][3], a1, b1[1], b1[3]);
            }
            b = (b == 2) ? 0 : b + 1;
        }

        // ---- epilogue ----
        if (role == 1) {
            // ih: pre[l][t] = acc + bias  (fp32, parity buffer)
            float* prew = g_pre + ((size_t)((t & 1) * LAYERS + l)) * BATCH * HID;
            #pragma unroll
            for (int mt = 0; mt < 2; mt++) {
                int rg = wm + mt * 16 + g;
                #pragma unroll
                for (int nti = 0; nti < 4; nti++) {
                    int cn = nt * 64 + wn + nti * 8 + tq * 2;
                    *(float2*)&prew[(size_t)rg * HID + cn] =
                        make_float2(acc[mt][nti][0] + bs[nti].x,
                                    acc[mt][nti][1] + bs[nti].y);
                    *(float2*)&prew[(size_t)(rg + 8) * HID + cn] =
                        make_float2(acc[mt][nti][2] + bs[nti].x,
                                    acc[mt][nti][3] + bs[nti].y);
                }
            }
        } else {
            // hh: h[l][t] = tanh(acc + pre[l][t]); write act (+ out for l=3)
            const float* prer = g_pre + ((size_t)((t & 1) * LAYERS + l)) * BATCH * HID;
            __half* actw = g_act[t & 1] + (size_t)l * BATCH * HID;
            #pragma unroll
            for (int mt = 0; mt < 2; mt++) {
                int rg = wm + mt * 16 + g;
                #pragma unroll
                for (int nti = 0; nti < 4; nti++) {
                    int cn = nt * 64 + wn + nti * 8 + tq * 2;
                    float2 p0 = __ldcg((const float2*)&prer[(size_t)rg * HID + cn]);
                    float2 p1 = __ldcg((const float2*)&prer[(size_t)(rg + 8) * HID + cn]);
                    float s0 = acc[mt][nti][0] + p0.x;
                    float s1 = acc[mt][nti][1] + p0.y;
                    float s2 = acc[mt][nti][2] + p1.x;
                    float s3 = acc[mt][nti][3] + p1.y;
                    float v0, v1, v2, v3;
                    if (l == 3) {
                        v0 = tanhf(s0); v1 = tanhf(s1);
                        v2 = tanhf(s2); v3 = tanhf(s3);
                    } else {
                        v0 = tanh_mufu(s0); v1 = tanh_mufu(s1);
                        v2 = tanh_mufu(s2); v3 = tanh_mufu(s3);
                    }
                    *(__half2*)&actw[(size_t)rg * HID + cn] =
                        __floats2half2_rn(v0, v1);
                    *(__half2*)&actw[(size_t)(rg + 8) * HID + cn] =
                        __floats2half2_rn(v2, v3);
                    if (l == 3) {
                        float* ob = out + (size_t)t * BATCH * HID + cn;
                        *(float2*)&ob[(size_t)rg * HID] = make_float2(v0, v1);
                        *(float2*)&ob[(size_t)(rg + 8) * HID] = make_float2(v2, v3);
                    }
                }
            }
        }

        // ---- publish progress ----
        __syncthreads();
        if (tid == 0) {
            __threadfence();
            atomicExch(&g_flags[bx * 32], (unsigned)(t + 1));
        }
    }
}

// -------------------------------------------------------------- launch ----
extern "C" void kernel_launch(void* const* d_in, const int* in_sizes, int n_in,
                              void* d_out, int out_size)
{
    const float* x   = (const float*)d_in[0];
    const float* Wih = (const float*)d_in[1];
    const float* Whh = (const float*)d_in[2];
    const float* bih = (const float*)d_in[3];
    const float* bhh = (const float*)d_in[4];
    float* out = (float*)d_out;

    cudaFuncSetAttribute(rnn_persistent,
                         cudaFuncAttributeMaxDynamicSharedMemorySize, SMEM_BYTES);

    prep_kernel<<<2048, 256>>>(x, Wih, Whh, bih, bhh);
    rnn_persistent<<<NCTA, 256, SMEM_BYTES>>>(out);
}